// round 12
// baseline (speedup 1.0000x reference)
#include <cuda_runtime.h>
#include <math.h>
#include <stdint.h>

#define GRID_N   160
#define NVOX     (160*160*160)
#define N_LORS   100000
#define EPS      1e-8f

// SIGMA = float32(300.0*0.15/2.355)
#define SIGMA_F     19.108280181884766f
#define C_HALF_F    0.15f
// Z2 cutoff 15: tail-linear error model (calibrated R8/R9): rel_err 1.95e-4,
// 5x margin under 1e-3. Do not tighten without re-measuring.
#define Z2_CUTOFF   15.0f
#define W_CUT       3.8729833462f               // sqrt(15)
#define S_HALFWIN   (W_CUT * SIGMA_F)           // 74.0mm
#define K_HL2E      0.72134752044f              // 0.5*log2(e)
#define SQRT_K      0.84932183f                 // sqrt(K_HL2E)
#define BOX_MARGIN  162.0f                      // FOV half-size + 1 voxel (conservative clip)

#define NSM          148
#define BLOCKS_PERSIST (NSM * 8)                // 8 blocks/SM resident

__device__ __forceinline__ float ex2f(float x) {
    float r; asm("ex2.approx.f32 %0, %1;" : "=f"(r) : "f"(x)); return r;
}

// ---------------------------------------------------------------------------
// Persistent warps: each warp grid-strides over LORs (removes block-drain
// imbalance from variable TOF-window sizes). One step per lane per span:
// k = kstart + lane + 32*j; spans contiguous -> BOTH the gather loop and the
// scatter loop break at the first dead span (staging is only initialized for
// active spans).
//
// Weight: w = 2^( log2(dl) - (z*sqrtK)^2 ), z' = fma(t, A, B) -> 2 FMA + EX2.
//
// Index path is BIT-EXACT vs the float32 reference (floor is discontinuous):
// SCALAR __fmul_rn/__fadd_rn ONLY. Packed f32x2 ops broke bit-exactness in
// R5 (rel_err 1.6e-3) — do NOT reintroduce them on this path.
//
// __launch_bounds__(256, 8): regs <=32 is the RF cap at 2048 thr/SM.
// Scatter stays plain per-lane (R9: shuffle-merge regressed).
// ---------------------------------------------------------------------------
__global__ void __launch_bounds__(256, 8)
lor_kernel(const float* __restrict__ image,
           const float* __restrict__ lors,
           float*       __restrict__ bp)
{
    const int lane   = threadIdx.x & 31;
    const int warp0  = (blockIdx.x * blockDim.x + threadIdx.x) >> 5;
    const int nwarps = (BLOCKS_PERSIST * 256) >> 5;

    for (int gwarp = warp0; gwarp < N_LORS; gwarp += nwarps) {

        // Broadcast the 7 LOR floats via lanes 0..6
        const float* l7 = lors + (size_t)gwarp * 7;
        float v = (lane < 7) ? __ldg(l7 + lane) : 0.0f;
        const float p0x = __shfl_sync(0xffffffffu, v, 0);
        const float p0y = __shfl_sync(0xffffffffu, v, 1);
        const float p0z = __shfl_sync(0xffffffffu, v, 2);
        const float p1x = __shfl_sync(0xffffffffu, v, 3);
        const float p1y = __shfl_sync(0xffffffffu, v, 4);
        const float p1z = __shfl_sync(0xffffffffu, v, 5);
        const float tof = __shfl_sync(0xffffffffu, v, 6);

        const float dx = p1x - p0x, dy = p1y - p0y, dz = p1z - p0z;
        const float L  = sqrtf(dx*dx + dy*dy + dz*dz);
        const float dl = L * 0.00390625f;
        const float s_tof = tof * C_HALF_F;

        // weight constants: z' = t*A + B;  arg = C - z'^2;  cut: arg > thresh
        const float A = L * (SQRT_K / SIGMA_F);
        const float B = -(0.5f * L + s_tof) * (SQRT_K / SIGMA_F);
        const float C = __log2f(dl);                // -inf if L==0 -> w=0
        const float thresh = C - Z2_CUTOFF * K_HL2E;

        // (a) TOF window in k-space
        const float invL  = __fdividef(1.0f, L);
        const float klo_f = fmaf((s_tof - S_HALFWIN) * invL, 256.0f, 127.5f);
        const float khi_f = fmaf((s_tof + S_HALFWIN) * invL, 256.0f, 127.5f);
        int kstart = (int)fmaxf(0.0f, fminf(255.0f, klo_f));
        int khi    = (int)fmaxf(0.0f, fminf(255.0f, khi_f));

        // (b) conservative ray-box clip: p0 + t*d in [-162,162]^3, t in [0,1]
        {
            const float ivx = __fdividef(1.0f, dx);
            const float ivy = __fdividef(1.0f, dy);
            const float ivz = __fdividef(1.0f, dz);
            const float ax0 = (-BOX_MARGIN - p0x) * ivx, ax1 = (BOX_MARGIN - p0x) * ivx;
            const float ay0 = (-BOX_MARGIN - p0y) * ivy, ay1 = (BOX_MARGIN - p0y) * ivy;
            const float az0 = (-BOX_MARGIN - p0z) * ivz, az1 = (BOX_MARGIN - p0z) * ivz;
            float tmin = fmaxf(fmaxf(fminf(ax0, ax1), fminf(ay0, ay1)),
                               fmaxf(fminf(az0, az1), 0.0f));
            float tmax = fminf(fminf(fmaxf(ax0, ax1), fmaxf(ay0, ay1)),
                               fminf(fmaxf(az0, az1), 1.0f));
            const int kbox_lo = (int)fmaxf(0.0f, fminf(255.0f, fmaf(tmin, 256.0f, -0.5f)));
            const int kbox_hi = (int)fmaxf(0.0f, fminf(255.0f, fmaf(tmax, 256.0f, -0.5f))) + 1;
            kstart = max(kstart, kbox_lo);
            khi    = min(khi, kbox_hi);
            if (tmin > tmax) { kstart = 1; khi = 0; }   // no intersection
        }

        // t exact: (k + 0.5) * 2^-8; += 0.125 per span is exact
        float t = ((float)(kstart + lane) + 0.5f) * 0.00390625f;

        int   fl[8];
        float wv[8];
        float p = 0.0f;

        #pragma unroll
        for (int j = 0; j < 8; ++j) {
            if (kstart + j * 32 > khi) break;  // warp-uniform, spans contiguous

            wv[j] = 0.0f;                      // init only for active spans
            fl[j] = 0;

            const float zp  = fmaf(t, A, B);
            const float arg = fmaf(zp, -zp, C);

            // pts = p0 + t*d — two roundings, exactly like the float32 reference
            const float px = __fadd_rn(p0x, __fmul_rn(t, dx));
            const float py = __fadd_rn(p0y, __fmul_rn(t, dy));
            const float pz = __fadd_rn(p0z, __fmul_rn(t, dz));
            // idx = floor((pts + 160) * 0.5) — exact ops vs reference's /2
            const int ix = (int)floorf(__fmul_rn(__fadd_rn(px, 160.0f), 0.5f));
            const int iy = (int)floorf(__fmul_rn(__fadd_rn(py, 160.0f), 0.5f));
            const int iz = (int)floorf(__fmul_rn(__fadd_rn(pz, 160.0f), 0.5f));

            // unsigned max-reduce bounds check (negatives wrap to huge)
            const unsigned mx = max(max((unsigned)ix, (unsigned)iy), (unsigned)iz);
            const bool ok = (mx < (unsigned)GRID_N) & (arg > thresh) & (t < 1.0f);
            if (ok) {
                const float ww = ex2f(arg);
                const int   f  = (ix * GRID_N + iy) * GRID_N + iz;
                p += __ldg(image + f) * ww;
                wv[j] = ww;
                fl[j] = f;
            }
            t += 0.125f;                       // exact
        }

        // Warp-reduce p
        #pragma unroll
        for (int off = 16; off > 0; off >>= 1)
            p += __shfl_xor_sync(0xffffffffu, p, off);

        // Scatter — same break condition, so only active spans are visited
        #pragma unroll
        for (int j = 0; j < 8; ++j) {
            if (kstart + j * 32 > khi) break;
            if (wv[j] != 0.0f)
                atomicAdd(bp + fl[j], p * wv[j]);
        }
    }
}

// ---------------------------------------------------------------------------
// Epilogue: out = image / (effmap + eps) * bp (in-place), 4 independent
// float4 streams per thread for memory-level parallelism.
// ---------------------------------------------------------------------------
#define N4  (NVOX / 4)        // 1024000
#define N4Q (N4 / 4)          // 256000

__global__ void __launch_bounds__(256)
finish_kernel(const float* __restrict__ image,
              const float* __restrict__ effmap,
              float*       __restrict__ out)
{
    const int i = blockIdx.x * blockDim.x + threadIdx.x;
    if (i >= N4Q) return;

    #pragma unroll
    for (int s = 0; s < 4; ++s) {
        const int idx = i + s * N4Q;
        float4 im = __ldg((const float4*)image  + idx);
        float4 ef = __ldg((const float4*)effmap + idx);
        float4 b  = ((const float4*)out)[idx];
        float4 r;
        r.x = __fdividef(im.x, ef.x + EPS) * b.x;
        r.y = __fdividef(im.y, ef.y + EPS) * b.y;
        r.z = __fdividef(im.z, ef.z + EPS) * b.z;
        r.w = __fdividef(im.w, ef.w + EPS) * b.w;
        ((float4*)out)[idx] = r;
    }
}

// Keeps ncu -s 5 -c 1 aligned on lor_kernel (4 launches/replay).
__global__ void probe_kernel() {}

extern "C" void kernel_launch(void* const* d_in, const int* in_sizes, int n_in,
                              void* d_out, int out_size)
{
    const float* image  = (const float*)d_in[0];
    const float* effmap = (const float*)d_in[1];
    const float* lors   = (const float*)d_in[2];
    float* out = (float*)d_out;

    cudaMemsetAsync(out, 0, (size_t)NVOX * sizeof(float), 0);

    lor_kernel<<<BLOCKS_PERSIST, 256>>>(image, lors, out);

    finish_kernel<<<(N4Q + 255) / 256, 256>>>(image, effmap, out);

    probe_kernel<<<1, 1>>>();
}

// round 13
// speedup vs baseline: 1.2370x; 1.2370x over previous
#include <cuda_runtime.h>
#include <math.h>
#include <stdint.h>

#define GRID_N   160
#define NVOX     (160*160*160)
#define N_LORS   100000
#define EPS      1e-8f

// SIGMA = float32(300.0*0.15/2.355)
#define SIGMA_F     19.108280181884766f
#define C_HALF_F    0.15f
// Z2 cutoff 15: tail-linear error model (calibrated R8/R9): rel_err 1.95e-4,
// 5x margin under 1e-3. Do not tighten without re-measuring.
#define Z2_CUTOFF   15.0f
#define W_CUT       3.8729833462f               // sqrt(15)
#define S_HALFWIN   (W_CUT * SIGMA_F)           // 74.0mm
#define K_HL2E      0.72134752044f              // 0.5*log2(e)
#define SQRT_K      0.84932183f                 // sqrt(K_HL2E)
#define BOX_MARGIN  162.0f                      // FOV half-size + 1 voxel (conservative clip)

__device__ __forceinline__ float ex2f(float x) {
    float r; asm("ex2.approx.f32 %0, %1;" : "=f"(r) : "f"(x)); return r;
}

// ---------------------------------------------------------------------------
// FIXED GRID, one warp per LOR (R12 lesson: persistent warps serialize LORs
// into one dependency chain -> issue 73%->52%. This kernel needs many
// independent short warps; the wave scheduler absorbs imbalance fine).
//
// One step per lane per span: k = kstart + lane + 32*j; spans contiguous ->
// gather AND scatter loops break at first dead span; staging initialized
// lazily (only for active spans).
//
// Weight: w = 2^( log2(dl) - (z*sqrtK)^2 ), z' = fma(t, A, B) -> 2 FMA + EX2.
//
// Index path is BIT-EXACT vs the float32 reference (floor is discontinuous):
// SCALAR __fmul_rn/__fadd_rn ONLY. Packed f32x2 ops broke bit-exactness in
// R5 (rel_err 1.6e-3) — do NOT reintroduce them on this path.
//
// __launch_bounds__(256, 8): regs <=32 is the RF cap at 2048 thr/SM (R6:
// regs 38 -> occ 56% -> regression). Scatter stays plain per-lane (R9:
// shuffle-merge regressed).
// ---------------------------------------------------------------------------
__global__ void __launch_bounds__(256, 8)
lor_kernel(const float* __restrict__ image,
           const float* __restrict__ lors,
           float*       __restrict__ bp)
{
    const int gwarp = (blockIdx.x * blockDim.x + threadIdx.x) >> 5;
    const int lane  = threadIdx.x & 31;
    if (gwarp >= N_LORS) return;

    // Broadcast the 7 LOR floats via lanes 0..6
    const float* l7 = lors + (size_t)gwarp * 7;
    float v = (lane < 7) ? __ldg(l7 + lane) : 0.0f;
    const float p0x = __shfl_sync(0xffffffffu, v, 0);
    const float p0y = __shfl_sync(0xffffffffu, v, 1);
    const float p0z = __shfl_sync(0xffffffffu, v, 2);
    const float p1x = __shfl_sync(0xffffffffu, v, 3);
    const float p1y = __shfl_sync(0xffffffffu, v, 4);
    const float p1z = __shfl_sync(0xffffffffu, v, 5);
    const float tof = __shfl_sync(0xffffffffu, v, 6);

    const float dx = p1x - p0x, dy = p1y - p0y, dz = p1z - p0z;
    const float L  = sqrtf(dx*dx + dy*dy + dz*dz);
    const float dl = L * 0.00390625f;
    const float s_tof = tof * C_HALF_F;

    // weight constants: z' = t*A + B;  arg = C - z'^2;  cut: arg > thresh
    const float A = L * (SQRT_K / SIGMA_F);
    const float B = -(0.5f * L + s_tof) * (SQRT_K / SIGMA_F);
    const float C = __log2f(dl);                    // -inf if L==0 -> w=0
    const float thresh = C - Z2_CUTOFF * K_HL2E;

    // (a) TOF window in k-space
    const float invL  = __fdividef(1.0f, L);
    const float klo_f = fmaf((s_tof - S_HALFWIN) * invL, 256.0f, 127.5f);
    const float khi_f = fmaf((s_tof + S_HALFWIN) * invL, 256.0f, 127.5f);
    int kstart = (int)fmaxf(0.0f, fminf(255.0f, klo_f));
    int khi    = (int)fmaxf(0.0f, fminf(255.0f, khi_f));

    // (b) conservative ray-box clip: p0 + t*d in [-162,162]^3, t in [0,1]
    {
        const float ivx = __fdividef(1.0f, dx);
        const float ivy = __fdividef(1.0f, dy);
        const float ivz = __fdividef(1.0f, dz);
        const float ax0 = (-BOX_MARGIN - p0x) * ivx, ax1 = (BOX_MARGIN - p0x) * ivx;
        const float ay0 = (-BOX_MARGIN - p0y) * ivy, ay1 = (BOX_MARGIN - p0y) * ivy;
        const float az0 = (-BOX_MARGIN - p0z) * ivz, az1 = (BOX_MARGIN - p0z) * ivz;
        float tmin = fmaxf(fmaxf(fminf(ax0, ax1), fminf(ay0, ay1)),
                           fmaxf(fminf(az0, az1), 0.0f));
        float tmax = fminf(fminf(fmaxf(ax0, ax1), fmaxf(ay0, ay1)),
                           fminf(fmaxf(az0, az1), 1.0f));
        const int kbox_lo = (int)fmaxf(0.0f, fminf(255.0f, fmaf(tmin, 256.0f, -0.5f)));
        const int kbox_hi = (int)fmaxf(0.0f, fminf(255.0f, fmaf(tmax, 256.0f, -0.5f))) + 1;
        kstart = max(kstart, kbox_lo);
        khi    = min(khi, kbox_hi);
        if (tmin > tmax) { kstart = 1; khi = 0; }   // no intersection
    }

    // t exact: (k + 0.5) * 2^-8; += 0.125 per span is exact
    float t = ((float)(kstart + lane) + 0.5f) * 0.00390625f;

    int   fl[8];
    float wv[8];
    float p = 0.0f;

    #pragma unroll
    for (int j = 0; j < 8; ++j) {
        if (kstart + j * 32 > khi) break;      // warp-uniform, spans contiguous

        wv[j] = 0.0f;                          // lazy init: active spans only
        fl[j] = 0;

        const float zp  = fmaf(t, A, B);
        const float arg = fmaf(zp, -zp, C);

        // pts = p0 + t*d — two roundings, exactly like the float32 reference
        const float px = __fadd_rn(p0x, __fmul_rn(t, dx));
        const float py = __fadd_rn(p0y, __fmul_rn(t, dy));
        const float pz = __fadd_rn(p0z, __fmul_rn(t, dz));
        // idx = floor((pts + 160) * 0.5) — exact ops vs reference's /2
        const int ix = (int)floorf(__fmul_rn(__fadd_rn(px, 160.0f), 0.5f));
        const int iy = (int)floorf(__fmul_rn(__fadd_rn(py, 160.0f), 0.5f));
        const int iz = (int)floorf(__fmul_rn(__fadd_rn(pz, 160.0f), 0.5f));

        // unsigned max-reduce bounds check (negatives wrap to huge)
        const unsigned mx = max(max((unsigned)ix, (unsigned)iy), (unsigned)iz);
        const bool ok = (mx < (unsigned)GRID_N) & (arg > thresh) & (t < 1.0f);
        if (ok) {
            const float ww = ex2f(arg);
            const int   f  = (ix * GRID_N + iy) * GRID_N + iz;
            p += __ldg(image + f) * ww;
            wv[j] = ww;
            fl[j] = f;
        }
        t += 0.125f;                           // exact
    }

    // Warp-reduce p
    #pragma unroll
    for (int off = 16; off > 0; off >>= 1)
        p += __shfl_xor_sync(0xffffffffu, p, off);

    // Scatter — same break condition: only active spans visited
    #pragma unroll
    for (int j = 0; j < 8; ++j) {
        if (kstart + j * 32 > khi) break;
        if (wv[j] != 0.0f)
            atomicAdd(bp + fl[j], p * wv[j]);
    }
}

// ---------------------------------------------------------------------------
// Epilogue: out = image / (effmap + eps) * bp (in-place), 4 independent
// float4 streams per thread for memory-level parallelism.
// ---------------------------------------------------------------------------
#define N4  (NVOX / 4)        // 1024000
#define N4Q (N4 / 4)          // 256000

__global__ void __launch_bounds__(256)
finish_kernel(const float* __restrict__ image,
              const float* __restrict__ effmap,
              float*       __restrict__ out)
{
    const int i = blockIdx.x * blockDim.x + threadIdx.x;
    if (i >= N4Q) return;

    #pragma unroll
    for (int s = 0; s < 4; ++s) {
        const int idx = i + s * N4Q;
        float4 im = __ldg((const float4*)image  + idx);
        float4 ef = __ldg((const float4*)effmap + idx);
        float4 b  = ((const float4*)out)[idx];
        float4 r;
        r.x = __fdividef(im.x, ef.x + EPS) * b.x;
        r.y = __fdividef(im.y, ef.y + EPS) * b.y;
        r.z = __fdividef(im.z, ef.z + EPS) * b.z;
        r.w = __fdividef(im.w, ef.w + EPS) * b.w;
        ((float4*)out)[idx] = r;
    }
}

// Keeps ncu -s 5 -c 1 aligned on lor_kernel (4 launches/replay).
__global__ void probe_kernel() {}

extern "C" void kernel_launch(void* const* d_in, const int* in_sizes, int n_in,
                              void* d_out, int out_size)
{
    const float* image  = (const float*)d_in[0];
    const float* effmap = (const float*)d_in[1];
    const float* lors   = (const float*)d_in[2];
    float* out = (float*)d_out;

    cudaMemsetAsync(out, 0, (size_t)NVOX * sizeof(float), 0);

    const int threads = 256;
    const int blocks  = (N_LORS * 32 + threads - 1) / threads;
    lor_kernel<<<blocks, threads>>>(image, lors, out);

    finish_kernel<<<(N4Q + 255) / 256, 256>>>(image, effmap, out);

    probe_kernel<<<1, 1>>>();
}

// round 14
// speedup vs baseline: 1.2741x; 1.0300x over previous
#include <cuda_runtime.h>
#include <math.h>
#include <stdint.h>

#define GRID_N   160
#define NVOX     (160*160*160)
#define N_LORS   100000
#define EPS      1e-8f

// SIGMA = float32(300.0*0.15/2.355)
#define SIGMA_F     19.108280181884766f
#define C_HALF_F    0.15f
// Z2 cutoff 15: tail-linear error model (calibrated R8/R9): rel_err 1.95e-4,
// 5x margin under 1e-3. Do not tighten without re-measuring.
#define Z2_CUTOFF   15.0f
#define W_CUT       3.8729833462f               // sqrt(15)
#define S_HALFWIN   (W_CUT * SIGMA_F)           // 74.0mm
#define K_HL2E      0.72134752044f              // 0.5*log2(e)
#define SQRT_K      0.84932183f                 // sqrt(K_HL2E)
#define BOX_MARGIN  162.0f                      // FOV half-size + 1 voxel (conservative clip)

__device__ __forceinline__ float ex2f(float x) {
    float r; asm("ex2.approx.f32 %0, %1;" : "=f"(r) : "f"(x)); return r;
}

// ---------------------------------------------------------------------------
// FIXED GRID, one warp per LOR (R12: persistent warps serialize LORs ->
// issue collapse; keep many independent short warps).
//
// One step per lane per span: k = kstart + lane + 32*j; spans contiguous ->
// gather AND scatter loops break at first dead span; staging lazy-init.
//
// R13 showed the kernel is now LTS-atomic-ALU bound (L2 73% vs issue 64%):
// scatter uses even-odd pair merging (consecutive steps share a voxel ~15%
// of the time), trading slack issue slots for atomic count. (R9 tried this
// when issue was the bind and lost; the balance has flipped.)
//
// Weight: w = 2^( log2(dl) - (z*sqrtK)^2 ), z' = fma(t, A, B) -> 2 FMA + EX2.
//
// Index path is BIT-EXACT vs the float32 reference (floor is discontinuous):
// SCALAR __fmul_rn/__fadd_rn ONLY. Packed f32x2 ops broke bit-exactness in
// R5 (rel_err 1.6e-3) — do NOT reintroduce them on this path.
//
// __launch_bounds__(256, 8): regs <=32 is the RF cap at 2048 thr/SM.
// ---------------------------------------------------------------------------
__global__ void __launch_bounds__(256, 8)
lor_kernel(const float* __restrict__ image,
           const float* __restrict__ lors,
           float*       __restrict__ bp)
{
    const int gwarp = (blockIdx.x * blockDim.x + threadIdx.x) >> 5;
    const int lane  = threadIdx.x & 31;
    if (gwarp >= N_LORS) return;

    // Broadcast the 7 LOR floats via lanes 0..6
    const float* l7 = lors + (size_t)gwarp * 7;
    float v = (lane < 7) ? __ldg(l7 + lane) : 0.0f;
    const float p0x = __shfl_sync(0xffffffffu, v, 0);
    const float p0y = __shfl_sync(0xffffffffu, v, 1);
    const float p0z = __shfl_sync(0xffffffffu, v, 2);
    const float p1x = __shfl_sync(0xffffffffu, v, 3);
    const float p1y = __shfl_sync(0xffffffffu, v, 4);
    const float p1z = __shfl_sync(0xffffffffu, v, 5);
    const float tof = __shfl_sync(0xffffffffu, v, 6);

    const float dx = p1x - p0x, dy = p1y - p0y, dz = p1z - p0z;
    const float L  = sqrtf(dx*dx + dy*dy + dz*dz);
    const float dl = L * 0.00390625f;
    const float s_tof = tof * C_HALF_F;

    // weight constants: z' = t*A + B;  arg = C - z'^2;  cut: arg > thresh
    const float A = L * (SQRT_K / SIGMA_F);
    const float B = -(0.5f * L + s_tof) * (SQRT_K / SIGMA_F);
    const float C = __log2f(dl);                    // -inf if L==0 -> w=0
    const float thresh = C - Z2_CUTOFF * K_HL2E;

    // (a) TOF window in k-space
    const float invL  = __fdividef(1.0f, L);
    const float klo_f = fmaf((s_tof - S_HALFWIN) * invL, 256.0f, 127.5f);
    const float khi_f = fmaf((s_tof + S_HALFWIN) * invL, 256.0f, 127.5f);
    int kstart = (int)fmaxf(0.0f, fminf(255.0f, klo_f));
    int khi    = (int)fmaxf(0.0f, fminf(255.0f, khi_f));

    // (b) conservative ray-box clip: p0 + t*d in [-162,162]^3, t in [0,1]
    {
        const float ivx = __fdividef(1.0f, dx);
        const float ivy = __fdividef(1.0f, dy);
        const float ivz = __fdividef(1.0f, dz);
        const float ax0 = (-BOX_MARGIN - p0x) * ivx, ax1 = (BOX_MARGIN - p0x) * ivx;
        const float ay0 = (-BOX_MARGIN - p0y) * ivy, ay1 = (BOX_MARGIN - p0y) * ivy;
        const float az0 = (-BOX_MARGIN - p0z) * ivz, az1 = (BOX_MARGIN - p0z) * ivz;
        float tmin = fmaxf(fmaxf(fminf(ax0, ax1), fminf(ay0, ay1)),
                           fmaxf(fminf(az0, az1), 0.0f));
        float tmax = fminf(fminf(fmaxf(ax0, ax1), fmaxf(ay0, ay1)),
                           fminf(fmaxf(az0, az1), 1.0f));
        const int kbox_lo = (int)fmaxf(0.0f, fminf(255.0f, fmaf(tmin, 256.0f, -0.5f)));
        const int kbox_hi = (int)fmaxf(0.0f, fminf(255.0f, fmaf(tmax, 256.0f, -0.5f))) + 1;
        kstart = max(kstart, kbox_lo);
        khi    = min(khi, kbox_hi);
        if (tmin > tmax) { kstart = 1; khi = 0; }   // no intersection
    }

    // t exact: (k + 0.5) * 2^-8; += 0.125 per span is exact
    float t = ((float)(kstart + lane) + 0.5f) * 0.00390625f;

    int   fl[8];
    float wv[8];
    float p = 0.0f;

    #pragma unroll
    for (int j = 0; j < 8; ++j) {
        if (kstart + j * 32 > khi) break;      // warp-uniform, spans contiguous

        wv[j] = 0.0f;                          // lazy init: active spans only
        fl[j] = 0;

        const float zp  = fmaf(t, A, B);
        const float arg = fmaf(zp, -zp, C);

        // pts = p0 + t*d — two roundings, exactly like the float32 reference
        const float px = __fadd_rn(p0x, __fmul_rn(t, dx));
        const float py = __fadd_rn(p0y, __fmul_rn(t, dy));
        const float pz = __fadd_rn(p0z, __fmul_rn(t, dz));
        // idx = floor((pts + 160) * 0.5) — exact ops vs reference's /2
        const int ix = (int)floorf(__fmul_rn(__fadd_rn(px, 160.0f), 0.5f));
        const int iy = (int)floorf(__fmul_rn(__fadd_rn(py, 160.0f), 0.5f));
        const int iz = (int)floorf(__fmul_rn(__fadd_rn(pz, 160.0f), 0.5f));

        // unsigned max-reduce bounds check (negatives wrap to huge)
        const unsigned mx = max(max((unsigned)ix, (unsigned)iy), (unsigned)iz);
        const bool ok = (mx < (unsigned)GRID_N) & (arg > thresh) & (t < 1.0f);
        if (ok) {
            const float ww = ex2f(arg);
            const int   f  = (ix * GRID_N + iy) * GRID_N + iz;
            p += __ldg(image + f) * ww;
            wv[j] = ww;
            fl[j] = f;
        }
        t += 0.125f;                           // exact
    }

    // Warp-reduce p
    #pragma unroll
    for (int off = 16; off > 0; off >>= 1)
        p += __shfl_xor_sync(0xffffffffu, p, off);

    // Scatter with even-odd pair merging (breaks with the gather loop).
    // Lanes (2i, 2i+1) hold consecutive steps; if same voxel, even lane
    // carries both weights. Both-dead pairs merge to 0 and are skipped.
    const bool even = !(lane & 1);
    #pragma unroll
    for (int j = 0; j < 8; ++j) {
        if (kstart + j * 32 > khi) break;
        const int   fj  = fl[j];
        const float wj  = wv[j];
        const int   f_o = __shfl_xor_sync(0xffffffffu, fj, 1);
        const float w_o = __shfl_xor_sync(0xffffffffu, wj, 1);
        const float ws  = (fj == f_o) ? (even ? wj + w_o : 0.0f) : wj;
        if (ws != 0.0f)
            atomicAdd(bp + fj, p * ws);
    }
}

// ---------------------------------------------------------------------------
// Epilogue: out = image / (effmap + eps) * bp (in-place), 4 independent
// float4 streams per thread for memory-level parallelism.
// ---------------------------------------------------------------------------
#define N4  (NVOX / 4)        // 1024000
#define N4Q (N4 / 4)          // 256000

__global__ void __launch_bounds__(256)
finish_kernel(const float* __restrict__ image,
              const float* __restrict__ effmap,
              float*       __restrict__ out)
{
    const int i = blockIdx.x * blockDim.x + threadIdx.x;
    if (i >= N4Q) return;

    #pragma unroll
    for (int s = 0; s < 4; ++s) {
        const int idx = i + s * N4Q;
        float4 im = __ldg((const float4*)image  + idx);
        float4 ef = __ldg((const float4*)effmap + idx);
        float4 b  = ((const float4*)out)[idx];
        float4 r;
        r.x = __fdividef(im.x, ef.x + EPS) * b.x;
        r.y = __fdividef(im.y, ef.y + EPS) * b.y;
        r.z = __fdividef(im.z, ef.z + EPS) * b.z;
        r.w = __fdividef(im.w, ef.w + EPS) * b.w;
        ((float4*)out)[idx] = r;
    }
}

// Keeps ncu -s 5 -c 1 aligned on lor_kernel (4 launches/replay).
__global__ void probe_kernel() {}

extern "C" void kernel_launch(void* const* d_in, const int* in_sizes, int n_in,
                              void* d_out, int out_size)
{
    const float* image  = (const float*)d_in[0];
    const float* effmap = (const float*)d_in[1];
    const float* lors   = (const float*)d_in[2];
    float* out = (float*)d_out;

    cudaMemsetAsync(out, 0, (size_t)NVOX * sizeof(float), 0);

    const int threads = 256;
    const int blocks  = (N_LORS * 32 + threads - 1) / threads;
    lor_kernel<<<blocks, threads>>>(image, lors, out);

    finish_kernel<<<(N4Q + 255) / 256, 256>>>(image, effmap, out);

    probe_kernel<<<1, 1>>>();
}

// round 15
// speedup vs baseline: 1.2816x; 1.0059x over previous
#include <cuda_runtime.h>
#include <math.h>
#include <stdint.h>

#define GRID_N   160
#define NVOX     (160*160*160)
#define N_LORS   100000
#define EPS      1e-8f

// SIGMA = float32(300.0*0.15/2.355)
#define SIGMA_F     19.108280181884766f
#define C_HALF_F    0.15f
// Z2 cutoff 14: err model err=1.83*tail (calibrated at Z2=18: 4.03e-5 and
// Z2=15: 1.95e-4, both exact) -> predicted 3.3e-4, 3x margin under 1e-3.
// Hard floor: do NOT go below 14 (Z2=13 -> 5.7e-4, margin <2x).
#define Z2_CUTOFF   14.0f
#define W_CUT       3.7416573868f               // sqrt(14)
#define S_HALFWIN   (W_CUT * SIGMA_F)           // 71.5mm
#define K_HL2E      0.72134752044f              // 0.5*log2(e)
#define SQRT_K      0.84932183f                 // sqrt(K_HL2E)
#define BOX_MARGIN  162.0f                      // FOV half-size + 1 voxel (conservative clip)

__device__ __forceinline__ float ex2f(float x) {
    float r; asm("ex2.approx.f32 %0, %1;" : "=f"(r) : "f"(x)); return r;
}

// ---------------------------------------------------------------------------
// FIXED GRID, one warp per LOR (R12: persistent warps serialize LORs ->
// issue collapse; keep many independent short warps).
//
// One step per lane per span: k = kstart + lane + 32*j; spans contiguous ->
// gather AND scatter loops break at first dead span; staging lazy-init.
//
// L2 (LTS) is the leading bind: unique gather sectors + atomic ops. Scatter
// uses even-odd pair merging (R14: L2 73->70%). Same-address gathers within
// a warp coalesce in L1TEX automatically — gather traffic is at its floor
// per sample; only sample count reduces it further.
//
// Weight: w = 2^( log2(dl) - (z*sqrtK)^2 ), z' = fma(t, A, B) -> 2 FMA + EX2.
//
// Index path is BIT-EXACT vs the float32 reference (floor is discontinuous):
// SCALAR __fmul_rn/__fadd_rn ONLY. Packed f32x2 ops broke bit-exactness in
// R5 (rel_err 1.6e-3) — do NOT reintroduce them on this path.
//
// __launch_bounds__(256, 8): regs <=32 is the RF cap at 2048 thr/SM.
// ---------------------------------------------------------------------------
__global__ void __launch_bounds__(256, 8)
lor_kernel(const float* __restrict__ image,
           const float* __restrict__ lors,
           float*       __restrict__ bp)
{
    const int gwarp = (blockIdx.x * blockDim.x + threadIdx.x) >> 5;
    const int lane  = threadIdx.x & 31;
    if (gwarp >= N_LORS) return;

    // Broadcast the 7 LOR floats via lanes 0..6
    const float* l7 = lors + (size_t)gwarp * 7;
    float v = (lane < 7) ? __ldg(l7 + lane) : 0.0f;
    const float p0x = __shfl_sync(0xffffffffu, v, 0);
    const float p0y = __shfl_sync(0xffffffffu, v, 1);
    const float p0z = __shfl_sync(0xffffffffu, v, 2);
    const float p1x = __shfl_sync(0xffffffffu, v, 3);
    const float p1y = __shfl_sync(0xffffffffu, v, 4);
    const float p1z = __shfl_sync(0xffffffffu, v, 5);
    const float tof = __shfl_sync(0xffffffffu, v, 6);

    const float dx = p1x - p0x, dy = p1y - p0y, dz = p1z - p0z;
    const float L  = sqrtf(dx*dx + dy*dy + dz*dz);
    const float dl = L * 0.00390625f;
    const float s_tof = tof * C_HALF_F;

    // weight constants: z' = t*A + B;  arg = C - z'^2;  cut: arg > thresh
    const float A = L * (SQRT_K / SIGMA_F);
    const float B = -(0.5f * L + s_tof) * (SQRT_K / SIGMA_F);
    const float C = __log2f(dl);                    // -inf if L==0 -> w=0
    const float thresh = C - Z2_CUTOFF * K_HL2E;

    // (a) TOF window in k-space
    const float invL  = __fdividef(1.0f, L);
    const float klo_f = fmaf((s_tof - S_HALFWIN) * invL, 256.0f, 127.5f);
    const float khi_f = fmaf((s_tof + S_HALFWIN) * invL, 256.0f, 127.5f);
    int kstart = (int)fmaxf(0.0f, fminf(255.0f, klo_f));
    int khi    = (int)fmaxf(0.0f, fminf(255.0f, khi_f));

    // (b) conservative ray-box clip: p0 + t*d in [-162,162]^3, t in [0,1]
    {
        const float ivx = __fdividef(1.0f, dx);
        const float ivy = __fdividef(1.0f, dy);
        const float ivz = __fdividef(1.0f, dz);
        const float ax0 = (-BOX_MARGIN - p0x) * ivx, ax1 = (BOX_MARGIN - p0x) * ivx;
        const float ay0 = (-BOX_MARGIN - p0y) * ivy, ay1 = (BOX_MARGIN - p0y) * ivy;
        const float az0 = (-BOX_MARGIN - p0z) * ivz, az1 = (BOX_MARGIN - p0z) * ivz;
        float tmin = fmaxf(fmaxf(fminf(ax0, ax1), fminf(ay0, ay1)),
                           fmaxf(fminf(az0, az1), 0.0f));
        float tmax = fminf(fminf(fmaxf(ax0, ax1), fmaxf(ay0, ay1)),
                           fminf(fmaxf(az0, az1), 1.0f));
        const int kbox_lo = (int)fmaxf(0.0f, fminf(255.0f, fmaf(tmin, 256.0f, -0.5f)));
        const int kbox_hi = (int)fmaxf(0.0f, fminf(255.0f, fmaf(tmax, 256.0f, -0.5f))) + 1;
        kstart = max(kstart, kbox_lo);
        khi    = min(khi, kbox_hi);
        if (tmin > tmax) { kstart = 1; khi = 0; }   // no intersection
    }

    // t exact: (k + 0.5) * 2^-8; += 0.125 per span is exact
    float t = ((float)(kstart + lane) + 0.5f) * 0.00390625f;

    int   fl[8];
    float wv[8];
    float p = 0.0f;

    #pragma unroll
    for (int j = 0; j < 8; ++j) {
        if (kstart + j * 32 > khi) break;      // warp-uniform, spans contiguous

        wv[j] = 0.0f;                          // lazy init: active spans only
        fl[j] = 0;

        const float zp  = fmaf(t, A, B);
        const float arg = fmaf(zp, -zp, C);

        // pts = p0 + t*d — two roundings, exactly like the float32 reference
        const float px = __fadd_rn(p0x, __fmul_rn(t, dx));
        const float py = __fadd_rn(p0y, __fmul_rn(t, dy));
        const float pz = __fadd_rn(p0z, __fmul_rn(t, dz));
        // idx = floor((pts + 160) * 0.5) — exact ops vs reference's /2
        const int ix = (int)floorf(__fmul_rn(__fadd_rn(px, 160.0f), 0.5f));
        const int iy = (int)floorf(__fmul_rn(__fadd_rn(py, 160.0f), 0.5f));
        const int iz = (int)floorf(__fmul_rn(__fadd_rn(pz, 160.0f), 0.5f));

        // unsigned max-reduce bounds check (negatives wrap to huge)
        const unsigned mx = max(max((unsigned)ix, (unsigned)iy), (unsigned)iz);
        const bool ok = (mx < (unsigned)GRID_N) & (arg > thresh) & (t < 1.0f);
        if (ok) {
            const float ww = ex2f(arg);
            const int   f  = (ix * GRID_N + iy) * GRID_N + iz;
            p += __ldg(image + f) * ww;
            wv[j] = ww;
            fl[j] = f;
        }
        t += 0.125f;                           // exact
    }

    // Warp-reduce p
    #pragma unroll
    for (int off = 16; off > 0; off >>= 1)
        p += __shfl_xor_sync(0xffffffffu, p, off);

    // Scatter with even-odd pair merging (breaks with the gather loop).
    // Lanes (2i, 2i+1) hold consecutive steps; if same voxel, even lane
    // carries both weights. Both-dead pairs merge to 0 and are skipped.
    const bool even = !(lane & 1);
    #pragma unroll
    for (int j = 0; j < 8; ++j) {
        if (kstart + j * 32 > khi) break;
        const int   fj  = fl[j];
        const float wj  = wv[j];
        const int   f_o = __shfl_xor_sync(0xffffffffu, fj, 1);
        const float w_o = __shfl_xor_sync(0xffffffffu, wj, 1);
        const float ws  = (fj == f_o) ? (even ? wj + w_o : 0.0f) : wj;
        if (ws != 0.0f)
            atomicAdd(bp + fj, p * ws);
    }
}

// ---------------------------------------------------------------------------
// Epilogue: out = image / (effmap + eps) * bp (in-place), 4 independent
// float4 streams per thread for memory-level parallelism.
// ---------------------------------------------------------------------------
#define N4  (NVOX / 4)        // 1024000
#define N4Q (N4 / 4)          // 256000

__global__ void __launch_bounds__(256)
finish_kernel(const float* __restrict__ image,
              const float* __restrict__ effmap,
              float*       __restrict__ out)
{
    const int i = blockIdx.x * blockDim.x + threadIdx.x;
    if (i >= N4Q) return;

    #pragma unroll
    for (int s = 0; s < 4; ++s) {
        const int idx = i + s * N4Q;
        float4 im = __ldg((const float4*)image  + idx);
        float4 ef = __ldg((const float4*)effmap + idx);
        float4 b  = __ldg((const float4*)out + idx);   // read-only before write
        float4 r;
        r.x = __fdividef(im.x, ef.x + EPS) * b.x;
        r.y = __fdividef(im.y, ef.y + EPS) * b.y;
        r.z = __fdividef(im.z, ef.z + EPS) * b.z;
        r.w = __fdividef(im.w, ef.w + EPS) * b.w;
        ((float4*)out)[idx] = r;
    }
}

extern "C" void kernel_launch(void* const* d_in, const int* in_sizes, int n_in,
                              void* d_out, int out_size)
{
    const float* image  = (const float*)d_in[0];
    const float* effmap = (const float*)d_in[1];
    const float* lors   = (const float*)d_in[2];
    float* out = (float*)d_out;

    cudaMemsetAsync(out, 0, (size_t)NVOX * sizeof(float), 0);

    const int threads = 256;
    const int blocks  = (N_LORS * 32 + threads - 1) / threads;
    lor_kernel<<<blocks, threads>>>(image, lors, out);

    finish_kernel<<<(N4Q + 255) / 256, 256>>>(image, effmap, out);
}

// round 16
// speedup vs baseline: 1.3377x; 1.0437x over previous
#include <cuda_runtime.h>
#include <math.h>
#include <stdint.h>

#define GRID_N   160
#define NVOX     (160*160*160)
#define N_LORS   100000
#define EPS      1e-8f

// SIGMA = float32(300.0*0.15/2.355)
#define SIGMA_F     19.108280181884766f
#define C_HALF_F    0.15f
// Z2 cutoff 14: err model err=1.83*tail, triple-calibrated (Z2=18: 4.03e-5,
// Z2=15: 1.95e-4, Z2=14: 3.299e-4 measured == predicted). 3x margin.
// HARD FLOOR — do not lower further.
#define Z2_CUTOFF   14.0f
#define W_CUT       3.7416573868f               // sqrt(14)
#define S_HALFWIN   (W_CUT * SIGMA_F)           // 71.5mm
#define K_HL2E      0.72134752044f              // 0.5*log2(e)
#define SQRT_K      0.84932183f                 // sqrt(K_HL2E)
#define BOX_MARGIN  162.0f                      // FOV half-size + 1 voxel (conservative clip)

__device__ __forceinline__ float ex2f(float x) {
    float r; asm("ex2.approx.f32 %0, %1;" : "=f"(r) : "f"(x)); return r;
}

// ---------------------------------------------------------------------------
// FIXED GRID, one warp per LOR (R12: persistent warps -> issue collapse).
// 128-thread blocks (16 resident/SM): finer-grain block retirement reduces
// drain waste from variable TOF-window lengths vs 256-thread blocks.
//
// One step per lane per span: k = kstart + lane + 32*j; spans contiguous ->
// gather AND scatter loops break at first dead span; staging lazy-init.
//
// L2 (LTS) is the leading bind (unique gather sectors + atomics). Scatter
// uses even-odd pair merging (R14: L2 73->70%).
//
// Weight: w = 2^( log2(dl) - (z*sqrtK)^2 ), z' = fma(t, A, B) -> 2 FMA + EX2.
//
// Index path is BIT-EXACT vs the float32 reference (floor is discontinuous):
// SCALAR __fmul_rn/__fadd_rn ONLY. Packed f32x2 ops broke bit-exactness in
// R5 (rel_err 1.6e-3) — do NOT reintroduce them on this path.
// ---------------------------------------------------------------------------
__global__ void __launch_bounds__(128, 16)
lor_kernel(const float* __restrict__ image,
           const float* __restrict__ lors,
           float*       __restrict__ bp)
{
    const int gwarp = (blockIdx.x * blockDim.x + threadIdx.x) >> 5;
    const int lane  = threadIdx.x & 31;
    if (gwarp >= N_LORS) return;

    // Broadcast the 7 LOR floats via lanes 0..6
    const float* l7 = lors + (size_t)gwarp * 7;
    float v = (lane < 7) ? __ldg(l7 + lane) : 0.0f;
    const float p0x = __shfl_sync(0xffffffffu, v, 0);
    const float p0y = __shfl_sync(0xffffffffu, v, 1);
    const float p0z = __shfl_sync(0xffffffffu, v, 2);
    const float p1x = __shfl_sync(0xffffffffu, v, 3);
    const float p1y = __shfl_sync(0xffffffffu, v, 4);
    const float p1z = __shfl_sync(0xffffffffu, v, 5);
    const float tof = __shfl_sync(0xffffffffu, v, 6);

    const float dx = p1x - p0x, dy = p1y - p0y, dz = p1z - p0z;
    const float L  = sqrtf(dx*dx + dy*dy + dz*dz);
    const float dl = L * 0.00390625f;
    const float s_tof = tof * C_HALF_F;

    // weight constants: z' = t*A + B;  arg = C - z'^2;  cut: arg > thresh
    const float A = L * (SQRT_K / SIGMA_F);
    const float B = -(0.5f * L + s_tof) * (SQRT_K / SIGMA_F);
    const float C = __log2f(dl);                    // -inf if L==0 -> w=0
    const float thresh = C - Z2_CUTOFF * K_HL2E;

    // (a) TOF window in k-space
    const float invL  = __fdividef(1.0f, L);
    const float klo_f = fmaf((s_tof - S_HALFWIN) * invL, 256.0f, 127.5f);
    const float khi_f = fmaf((s_tof + S_HALFWIN) * invL, 256.0f, 127.5f);
    int kstart = (int)fmaxf(0.0f, fminf(255.0f, klo_f));
    int khi    = (int)fmaxf(0.0f, fminf(255.0f, khi_f));

    // (b) conservative ray-box clip: p0 + t*d in [-162,162]^3, t in [0,1]
    {
        const float ivx = __fdividef(1.0f, dx);
        const float ivy = __fdividef(1.0f, dy);
        const float ivz = __fdividef(1.0f, dz);
        const float ax0 = (-BOX_MARGIN - p0x) * ivx, ax1 = (BOX_MARGIN - p0x) * ivx;
        const float ay0 = (-BOX_MARGIN - p0y) * ivy, ay1 = (BOX_MARGIN - p0y) * ivy;
        const float az0 = (-BOX_MARGIN - p0z) * ivz, az1 = (BOX_MARGIN - p0z) * ivz;
        float tmin = fmaxf(fmaxf(fminf(ax0, ax1), fminf(ay0, ay1)),
                           fmaxf(fminf(az0, az1), 0.0f));
        float tmax = fminf(fminf(fmaxf(ax0, ax1), fmaxf(ay0, ay1)),
                           fminf(fmaxf(az0, az1), 1.0f));
        const int kbox_lo = (int)fmaxf(0.0f, fminf(255.0f, fmaf(tmin, 256.0f, -0.5f)));
        const int kbox_hi = (int)fmaxf(0.0f, fminf(255.0f, fmaf(tmax, 256.0f, -0.5f))) + 1;
        kstart = max(kstart, kbox_lo);
        khi    = min(khi, kbox_hi);
        if (tmin > tmax) { kstart = 1; khi = 0; }   // no intersection
    }

    // t exact: (k + 0.5) * 2^-8; += 0.125 per span is exact
    float t = ((float)(kstart + lane) + 0.5f) * 0.00390625f;

    int   fl[8];
    float wv[8];
    float p = 0.0f;

    #pragma unroll
    for (int j = 0; j < 8; ++j) {
        if (kstart + j * 32 > khi) break;      // warp-uniform, spans contiguous

        wv[j] = 0.0f;                          // lazy init: active spans only
        fl[j] = 0;

        const float zp  = fmaf(t, A, B);
        const float arg = fmaf(zp, -zp, C);

        // pts = p0 + t*d — two roundings, exactly like the float32 reference
        const float px = __fadd_rn(p0x, __fmul_rn(t, dx));
        const float py = __fadd_rn(p0y, __fmul_rn(t, dy));
        const float pz = __fadd_rn(p0z, __fmul_rn(t, dz));
        // idx = floor((pts + 160) * 0.5) — exact ops vs reference's /2
        const int ix = (int)floorf(__fmul_rn(__fadd_rn(px, 160.0f), 0.5f));
        const int iy = (int)floorf(__fmul_rn(__fadd_rn(py, 160.0f), 0.5f));
        const int iz = (int)floorf(__fmul_rn(__fadd_rn(pz, 160.0f), 0.5f));

        // unsigned max-reduce bounds check (negatives wrap to huge)
        const unsigned mx = max(max((unsigned)ix, (unsigned)iy), (unsigned)iz);
        const bool ok = (mx < (unsigned)GRID_N) & (arg > thresh) & (t < 1.0f);
        if (ok) {
            const float ww = ex2f(arg);
            const int   f  = (ix * GRID_N + iy) * GRID_N + iz;
            p += __ldg(image + f) * ww;
            wv[j] = ww;
            fl[j] = f;
        }
        t += 0.125f;                           // exact
    }

    // Warp-reduce p
    #pragma unroll
    for (int off = 16; off > 0; off >>= 1)
        p += __shfl_xor_sync(0xffffffffu, p, off);

    // Scatter with even-odd pair merging (breaks with the gather loop).
    const bool even = !(lane & 1);
    #pragma unroll
    for (int j = 0; j < 8; ++j) {
        if (kstart + j * 32 > khi) break;
        const int   fj  = fl[j];
        const float wj  = wv[j];
        const int   f_o = __shfl_xor_sync(0xffffffffu, fj, 1);
        const float w_o = __shfl_xor_sync(0xffffffffu, wj, 1);
        const float ws  = (fj == f_o) ? (even ? wj + w_o : 0.0f) : wj;
        if (ws != 0.0f)
            atomicAdd(bp + fj, p * ws);
    }
}

// ---------------------------------------------------------------------------
// Epilogue: out = image / (effmap + eps) * bp (in-place), 2 float4 streams
// (R15: ILP4 at grid=1000 regressed — single ragged wave + 36 regs.
// ILP2/grid-2000 keeps occupancy and multi-wave balance).
// ---------------------------------------------------------------------------
#define N4      (NVOX / 4)        // 1024000
#define N4_HALF (N4 / 2)          // 512000

__global__ void __launch_bounds__(256)
finish_kernel(const float* __restrict__ image,
              const float* __restrict__ effmap,
              float*       __restrict__ out)
{
    const int i = blockIdx.x * blockDim.x + threadIdx.x;
    if (i >= N4_HALF) return;
    const int i2 = i + N4_HALF;

    float4 imA = __ldg((const float4*)image  + i);
    float4 efA = __ldg((const float4*)effmap + i);
    float4 bA  = __ldg((const float4*)out + i);
    float4 imB = __ldg((const float4*)image  + i2);
    float4 efB = __ldg((const float4*)effmap + i2);
    float4 bB  = __ldg((const float4*)out + i2);

    float4 rA, rB;
    rA.x = __fdividef(imA.x, efA.x + EPS) * bA.x;
    rA.y = __fdividef(imA.y, efA.y + EPS) * bA.y;
    rA.z = __fdividef(imA.z, efA.z + EPS) * bA.z;
    rA.w = __fdividef(imA.w, efA.w + EPS) * bA.w;
    rB.x = __fdividef(imB.x, efB.x + EPS) * bB.x;
    rB.y = __fdividef(imB.y, efB.y + EPS) * bB.y;
    rB.z = __fdividef(imB.z, efB.z + EPS) * bB.z;
    rB.w = __fdividef(imB.w, efB.w + EPS) * bB.w;

    ((float4*)out)[i]  = rA;
    ((float4*)out)[i2] = rB;
}

extern "C" void kernel_launch(void* const* d_in, const int* in_sizes, int n_in,
                              void* d_out, int out_size)
{
    const float* image  = (const float*)d_in[0];
    const float* effmap = (const float*)d_in[1];
    const float* lors   = (const float*)d_in[2];
    float* out = (float*)d_out;

    cudaMemsetAsync(out, 0, (size_t)NVOX * sizeof(float), 0);

    const int threads = 128;
    const int blocks  = (N_LORS * 32 + threads - 1) / threads;   // 25000
    lor_kernel<<<blocks, threads>>>(image, lors, out);

    finish_kernel<<<(N4_HALF + 255) / 256, 256>>>(image, effmap, out);
}